// round 14
// baseline (speedup 1.0000x reference)
#include <cuda_runtime.h>
#include <cstdint>

// Inputs (metadata order):
//   d_in[0] state           float32 [B, A, N, 3]
//   d_in[1] nodes_coords    float32 [P, 2]
//   d_in[2] adj             float32 [P, N]
//   d_in[3] node_last_visit int32   [B, A]
//   d_in[4] patrol_index    int32   [P]
// Output: float32 [B, A, N, 6]
//
// Per-warp fully-async pipeline:
//   TMA bulk-in (state slice 768B + adj slice 256B -> smem staging, mbarrier)
//   -> LDS/STS gather into output-image tile -> TMA bulk-out.
// Global LDGs removed from the hot path (no L1tex queue contention).

__global__ __launch_bounds__(128)
void policy_gather_kernel(const float* __restrict__ state,
                          const float* __restrict__ coords,
                          const float* __restrict__ adj,
                          const int*   __restrict__ nlv,
                          const int*   __restrict__ pidx,
                          float* __restrict__ out,
                          int N,
                          unsigned long long stateBytes,
                          unsigned long long adjBytes) {
    extern __shared__ __align__(16) unsigned char smem_raw[];
    // Layout: [0,64) 4 warp mbarriers (16B stride)
    //         [64, 64+24N) out tile
    //         then 4 x 800B state staging, 4 x 288B adj staging
    const int tileB  = (24 * N + 15) & ~15;
    const int ST_OFF = 64 + tileB;
    const int AD_OFF = ST_OFF + 4 * 800;

    const int t    = threadIdx.x;
    const int warp = t >> 5;
    const int lane = t & 31;
    const int row  = blockIdx.x;
    const int pairs = N >> 1;

    uint32_t smem_base;
    asm("{ .reg .u64 tmp; cvta.to.shared.u64 tmp, %1; cvt.u32.u64 %0, tmp; }"
        : "=r"(smem_base) : "l"(smem_raw));
    float* s_row = reinterpret_cast<float*>(smem_raw + 64);

    // Row-constant chain.
    const int   v   = __ldg(nlv + row);
    const int   idx = __ldg(pidx + v);
    const float zx  = __ldg(coords + 2 * v);
    const float zy  = __ldg(coords + 2 * v + 1);

    const float* __restrict__ st = state + (size_t)row * N * 3;
    const float* __restrict__ ar = adj   + (size_t)idx * N;
    float* __restrict__ orow     = out   + (size_t)row * N * 6;   // 16B aligned

    const bool okTMA = ((((uintptr_t)orow) & 0xF) == 0) && (pairs <= 128)
                       && (((((uintptr_t)st) | ((uintptr_t)ar)) & 7) == 0);

    if (okTMA) {
        const int start = warp * 32;
        const int cnt   = min(32, max(0, pairs - start));

        // This warp's slice byte ranges (offsets from array bases).
        const unsigned long long sByte = ((unsigned long long)row * N * 3 + (unsigned long long)start * 6) * 4;
        const unsigned long long aByte = ((unsigned long long)idx * N + (unsigned long long)start * 2) * 4;
        const unsigned long long sAl = sByte & ~15ULL;
        const unsigned long long aAl = aByte & ~15ULL;
        const int sOff = (int)(sByte & 15);
        const int aOff = (int)(aByte & 15);
        const int sLen = (sOff + cnt * 24 + 15) & ~15;
        const int aLen = (aOff + cnt * 8 + 15) & ~15;
        const bool okIn = (cnt > 0) && (sAl + sLen <= stateBytes) && (aAl + aLen <= adjBytes);

        if (okIn) {
            // --- TMA bulk-in path (per-warp) ---
            const uint32_t mbar  = smem_base + warp * 16;
            const uint32_t stg_s = smem_base + ST_OFF + warp * 800;
            const uint32_t stg_a = smem_base + AD_OFF + warp * 288;

            if (lane == 0) {
                asm volatile("mbarrier.init.shared.b64 [%0], 1;" :: "r"(mbar) : "memory");
            }
            __syncwarp();
            if (lane == 0) {
                asm volatile("mbarrier.arrive.expect_tx.shared.b64 _, [%0], %1;"
                             :: "r"(mbar), "r"((uint32_t)(sLen + aLen)) : "memory");
                asm volatile(
                    "cp.async.bulk.shared::cluster.global.mbarrier::complete_tx::bytes [%0], [%1], %2, [%3];"
                    :: "r"(stg_s), "l"((const char*)state + sAl), "r"((uint32_t)sLen), "r"(mbar) : "memory");
                asm volatile(
                    "cp.async.bulk.shared::cluster.global.mbarrier::complete_tx::bytes [%0], [%1], %2, [%3];"
                    :: "r"(stg_a), "l"((const char*)adj + aAl), "r"((uint32_t)aLen), "r"(mbar) : "memory");
            }
            // Wait (acquire orders the async writes before our LDS reads).
            {
                uint32_t done;
                asm volatile(
                    "{ .reg .pred p; mbarrier.try_wait.parity.acquire.cta.shared::cta.b64 p, [%1], 0; selp.b32 %0, 1, 0, p; }"
                    : "=r"(done) : "r"(mbar) : "memory");
                while (!done) {
                    asm volatile(
                        "{ .reg .pred p; mbarrier.try_wait.parity.acquire.cta.shared::cta.b64 p, [%1], 0, 0x989680; selp.b32 %0, 1, 0, p; }"
                        : "=r"(done) : "r"(mbar) : "memory");
                }
            }

            if (lane < cnt) {
                const int p = start + lane;
                const uint32_t sa = stg_s + sOff + lane * 24;
                const uint32_t aa_addr = stg_a + aOff + lane * 8;
                float s0,s1,s2,s3,s4,s5, a0,a1;
                asm volatile("ld.shared.v2.f32 {%0,%1}, [%2];"    : "=f"(s0), "=f"(s1) : "r"(sa));
                asm volatile("ld.shared.v2.f32 {%0,%1}, [%2+8];"  : "=f"(s2), "=f"(s3) : "r"(sa));
                asm volatile("ld.shared.v2.f32 {%0,%1}, [%2+16];" : "=f"(s4), "=f"(s5) : "r"(sa));
                asm volatile("ld.shared.v2.f32 {%0,%1}, [%2];"    : "=f"(a0), "=f"(a1) : "r"(aa_addr));

                float4* d = reinterpret_cast<float4*>(s_row + 12 * p);
                d[0] = make_float4(s0, s1, s2, zx);
                d[1] = make_float4(zy, a0, s3, s4);
                d[2] = make_float4(s5, zx, zy, a1);
            }
        } else if (cnt > 0) {
            // --- LDG fallback for edge warps (overread would exit allocation) ---
            if (lane < cnt) {
                const int p = start + lane;
                const float2 s01 = __ldcs(reinterpret_cast<const float2*>(st + 6 * p));
                const float2 s23 = __ldcs(reinterpret_cast<const float2*>(st + 6 * p + 2));
                const float2 s45 = __ldcs(reinterpret_cast<const float2*>(st + 6 * p + 4));
                const float2 aa  = __ldg (reinterpret_cast<const float2*>(ar + 2 * p));
                float4* d = reinterpret_cast<float4*>(s_row + 12 * p);
                d[0] = make_float4(s01.x, s01.y, s23.x, zx);
                d[1] = make_float4(zy,    aa.x,  s23.y, s45.x);
                d[2] = make_float4(s45.y, zx,    zy,    aa.y);
            }
        }

        __syncwarp();
        asm volatile("fence.proxy.async.shared::cta;" ::: "memory");

        if (cnt > 0 && lane == 0) {
            const unsigned bytes = (unsigned)(cnt * 48);
            float* gdst = orow + (size_t)start * 12;
            asm volatile(
                "cp.async.bulk.global.shared::cta.bulk_group [%0], [%1], %2;"
                :: "l"(gdst), "r"((uint32_t)(smem_base + 64 + 48 * start)), "r"(bytes) : "memory");
            asm volatile("cp.async.bulk.commit_group;" ::: "memory");
        }

        // Odd-N tail node.
        if ((N & 1) && t == 0) {
            const int n = N - 1;
            float* d = orow + 6 * n;
            __stcs(d + 0, st[3 * n + 0]);
            __stcs(d + 1, st[3 * n + 1]);
            __stcs(d + 2, st[3 * n + 2]);
            __stcs(d + 3, zx);
            __stcs(d + 4, zy);
            __stcs(d + 5, ar[n]);
        }

        if (lane == 0) {
            asm volatile("cp.async.bulk.wait_group.read 0;" ::: "memory");
        }
    } else {
        // Full scalar fallback (uniform condition across the block).
        for (int n = t; n < N; n += blockDim.x) {
            float* d = s_row + 6 * n;
            d[0] = st[3 * n + 0];
            d[1] = st[3 * n + 1];
            d[2] = st[3 * n + 2];
            d[3] = zx;
            d[4] = zy;
            d[5] = ar[n];
        }
        __syncthreads();
        const int total = N * 6;
        for (int j = t; j < total; j += blockDim.x) {
            __stcs(orow + j, s_row[j]);
        }
    }
}

extern "C" void kernel_launch(void* const* d_in, const int* in_sizes, int n_in,
                              void* d_out, int out_size) {
    const float* state  = (const float*)d_in[0];
    const float* coords = (const float*)d_in[1];
    const float* adj    = (const float*)d_in[2];
    const int*   nlv    = (const int*)d_in[3];
    const int*   pidx   = (const int*)d_in[4];
    float*       out    = (float*)d_out;

    const int BA = in_sizes[3];            // B * A rows
    const int P  = in_sizes[4];            // patrol nodes
    const int N  = in_sizes[2] / P;        // graph size (adj is [P, N])

    const unsigned long long stateBytes = (unsigned long long)in_sizes[0] * 4ULL;
    const unsigned long long adjBytes   = (unsigned long long)in_sizes[2] * 4ULL;

    const int tileB = (24 * N + 15) & ~15;
    const size_t smem = 64 + tileB + 4 * 800 + 4 * 288;

    policy_gather_kernel<<<BA, 128, smem>>>(state, coords, adj, nlv, pidx, out,
                                            N, stateBytes, adjBytes);
}

// round 15
// speedup vs baseline: 1.0371x; 1.0371x over previous
#include <cuda_runtime.h>
#include <cstdint>

// Inputs (metadata order):
//   d_in[0] state           float32 [B, A, N, 3]
//   d_in[1] nodes_coords    float32 [P, 2]
//   d_in[2] adj             float32 [P, N]
//   d_in[3] node_last_visit int32   [B, A]
//   d_in[4] patrol_index    int32   [P]
// Output: float32 [B, A, N, 6]
//
// R13 structure (best): one CTA/row, per-warp independent pipelines
// (LDG -> STS.128 -> per-warp TMA bulk store, no __syncthreads), plus
// L2 evict_first cache policy on the write-once output bulk stores.

__global__ __launch_bounds__(128)
void policy_gather_kernel(const float* __restrict__ state,
                          const float* __restrict__ coords,
                          const float* __restrict__ adj,
                          const int*   __restrict__ nlv,
                          const int*   __restrict__ pidx,
                          float* __restrict__ out,
                          int N) {
    extern __shared__ __align__(16) float s_row[];   // N*6 floats, output-row image

    const int row  = blockIdx.x;
    const int t    = threadIdx.x;
    const int warp = t >> 5;
    const int lane = t & 31;

    const float* __restrict__ st = state + (size_t)row * N * 3;   // 8B aligned
    float* __restrict__ orow     = out   + (size_t)row * N * 6;   // 16B aligned

    const bool okA   = ((((uintptr_t)st) & 7) == 0) && ((((uintptr_t)adj) & 7) == 0);
    const bool okTMA = ((((uintptr_t)orow) & 0xF) == 0);
    const int pairs  = N >> 1;

    if (okA && okTMA && pairs <= 128) {
        const int start = warp * 32;
        const int cnt   = pairs - start;            // lanes < cnt are active
        const int p     = start + lane;
        const bool act  = (lane < cnt);

        // Independent state loads FIRST: DRAM latency overlaps the chain below.
        float2 s01 = make_float2(0.f, 0.f), s23 = s01, s45 = s01;
        if (act) {
            s01 = __ldcs(reinterpret_cast<const float2*>(st + 6 * p));
            s23 = __ldcs(reinterpret_cast<const float2*>(st + 6 * p + 2));
            s45 = __ldcs(reinterpret_cast<const float2*>(st + 6 * p + 4));
        }

        // Row-constant chain, with speculative adj prefetch off v.
        const int v = __ldg(nlv + row);
        if (act) {
            const float* pf = adj + (size_t)v * N + 2 * p;
            asm volatile("prefetch.global.L1 [%0];" :: "l"(pf));
        }
        const int   idx = __ldg(pidx + v);
        const float zx  = __ldg(coords + 2 * v);
        const float zy  = __ldg(coords + 2 * v + 1);

        const float* __restrict__ ar = adj + (size_t)idx * N;      // 8B aligned

        if (act) {
            const float2 aa = __ldg(reinterpret_cast<const float2*>(ar + 2 * p));

            float4* d = reinterpret_cast<float4*>(s_row + 12 * p); // 16B aligned
            d[0] = make_float4(s01.x, s01.y, s23.x, zx);
            d[1] = make_float4(zy,    aa.x,  s23.y, s45.x);
            d[2] = make_float4(s45.y, zx,    zy,    aa.y);
        }
        __syncwarp();
        asm volatile("fence.proxy.async.shared::cta;" ::: "memory");

        if (cnt > 0 && lane == 0) {
            const int c = min(32, cnt);
            const unsigned bytes = (unsigned)(c * 12 * sizeof(float));  // mult of 48
            float* gdst = orow + (size_t)start * 12;
            uint32_t saddr;
            asm("{ .reg .u64 tmp; cvta.to.shared.u64 tmp, %1; cvt.u32.u64 %0, tmp; }"
                : "=r"(saddr) : "l"(s_row + 12 * start));
            // Write-once output: evict_first so these lines drain from L2
            // promptly instead of displacing the reused adj rows.
            uint64_t pol;
            asm volatile("createpolicy.fractional.L2::evict_first.b64 %0, 1.0;"
                         : "=l"(pol));
            asm volatile(
                "cp.async.bulk.global.shared::cta.bulk_group.L2::cache_hint "
                "[%0], [%1], %2, %3;"
                :: "l"(gdst), "r"(saddr), "r"(bytes), "l"(pol) : "memory");
            asm volatile("cp.async.bulk.commit_group;" ::: "memory");
        }

        // Odd-N tail node.
        if ((N & 1) && t == 0) {
            const int n = N - 1;
            float* dsc = orow + 6 * n;
            __stcs(dsc + 0, st[3 * n + 0]);
            __stcs(dsc + 1, st[3 * n + 1]);
            __stcs(dsc + 2, st[3 * n + 2]);
            __stcs(dsc + 3, zx);
            __stcs(dsc + 4, zy);
            __stcs(dsc + 5, ar[n]);
        }

        // Exit gate: smem READ completion only.
        if (lane == 0) {
            asm volatile("cp.async.bulk.wait_group.read 0;" ::: "memory");
        }
    } else {
        // Fallback: staged scalar copy with full-block sync.
        const int v   = __ldg(nlv + row);
        const int idx = __ldg(pidx + v);
        const float zx = __ldg(coords + 2 * v);
        const float zy = __ldg(coords + 2 * v + 1);
        const float* __restrict__ ar = adj + (size_t)idx * N;
        for (int n = t; n < N; n += blockDim.x) {
            float* d = s_row + 6 * n;
            d[0] = st[3 * n + 0];
            d[1] = st[3 * n + 1];
            d[2] = st[3 * n + 2];
            d[3] = zx;
            d[4] = zy;
            d[5] = ar[n];
        }
        __syncthreads();
        const int total = N * 6;
        for (int j = t; j < total; j += blockDim.x) {
            __stcs(orow + j, s_row[j]);
        }
    }
}

extern "C" void kernel_launch(void* const* d_in, const int* in_sizes, int n_in,
                              void* d_out, int out_size) {
    const float* state  = (const float*)d_in[0];
    const float* coords = (const float*)d_in[1];
    const float* adj    = (const float*)d_in[2];
    const int*   nlv    = (const int*)d_in[3];
    const int*   pidx   = (const int*)d_in[4];
    float*       out    = (float*)d_out;

    const int BA = in_sizes[3];            // B * A rows
    const int P  = in_sizes[4];            // patrol nodes
    const int N  = in_sizes[2] / P;        // graph size (adj is [P, N])

    const size_t smem = (size_t)N * 6 * sizeof(float);
    policy_gather_kernel<<<BA, 128, smem>>>(state, coords, adj, nlv, pidx, out, N);
}